// round 13
// baseline (speedup 1.0000x reference)
#include <cuda_runtime.h>
#include <math.h>

#define BB   16
#define CIN  64
#define COUT 64
#define HH   256
#define WW   256
#define NMODE 800        // 40 kx * 20 ky
#define NBI  1024        // B*CI
#define NBO  1024        // B*CO

__device__ float2 g_Xf[NMODE * NBI];       // [m][bi]  6.6 MB
__device__ float2 g_Yf[NBO * NMODE];       // [bo][m]  6.6 MB

// ---------------------------------------------------------------------------
// Kernel A: fused W-DFT + H-DFT for one (b,ci) image. 256 threads, 2 CTA/SM.
// (R8/R12 configuration: best measured 132.7 us. Unchanged.)
// ---------------------------------------------------------------------------
__global__ void __launch_bounds__(256, 2) stage12_fwd(const float* __restrict__ x) {
    extern __shared__ float smem[];
    float*  Ef  = smem;                            // [256*12]
    float*  Of  = smem + 3072;
    float*  EMf = smem + 6144;
    float*  OMf = smem + 9216;
    float4* tw4 = (float4*)(smem + 12288);         // [64][10]
    float2* eb  = (float2*)(smem + 14848);         // [256]
    float4* Xs4 = (float4*)smem;                   // [128][11] (phase-2 input)
    float4* Xd4 = Xs4 + 1408;

    const int bi  = blockIdx.x;
    const int t   = threadIdx.x;
    const int rp  = t & 127;
    const int kyh = t >> 7;                        // warp-uniform ky half

    for (int i = t; i < 640; i += 256) {
        int wi = i / 10 + 1, kk = i % 10;
        float s0, c0, s1, c1;
        sincospif((float)((2*kk    ) * wi) * (1.0f/128.0f), &s0, &c0);
        sincospif((float)((2*kk + 1) * wi) * (1.0f/128.0f), &s1, &c1);
        float hsc = (wi == 64) ? 0.5f : 1.0f;
        tw4[i] = make_float4(c0*hsc, s0*hsc, c1*hsc, s1*hsc);
    }
    {
        float s, c;
        sincospif((float)t * (1.0f/128.0f), &s, &c);
        eb[t] = make_float2(c, s);
    }

    const float* img = x + (size_t)bi * (HH*WW);

    float4 acc0[5], acc1[5];
    {
        float a0 = img[rp*WW],         b0 = img[rp*WW + 128];
        float a1 = img[(rp+128)*WW],   b1 = img[(rp+128)*WW + 128];
        float ue0 = a0 + b0, uo0 = a0 - b0;
        float ue1 = a1 + b1, uo1 = a1 - b1;
        #pragma unroll
        for (int k = 0; k < 5; k++) {
            acc0[k] = make_float4(ue0, 0.f, uo0, 0.f);   // w=0 term (c=1,s=0)
            acc1[k] = make_float4(ue1, 0.f, uo1, 0.f);
        }
    }

    for (int c = 0; c < 8; c++) {                  // chunks of 8 w, w = 1..64
        const int w0     = 1 + 8*c;
        const int mstart = 120 - 8*c;              // mirror window start
        __syncthreads();
        #pragma unroll
        for (int i = 0; i < 8; i++) {
            int idx = t + i*256;                   // 0..2047
            int r   = idx >> 3;
            int j   = idx & 7;
            const float* rpn = img + r * WW;
            float a1 = rpn[w0 + j],     b1 = rpn[w0 + j + 128];
            float a2 = rpn[mstart + j], b2 = rpn[mstart + j + 128];
            int s = r*12 + j;
            Ef[s]  = a1 + b1;  Of[s]  = a1 - b1;
            EMf[s] = a2 + b2;  OMf[s] = a2 - b2;
        }
        __syncthreads();

        const float4* E4  = (const float4*)Ef;
        const float4* O4  = (const float4*)Of;
        const float4* EM4 = (const float4*)EMf;
        const float4* OM4 = (const float4*)OMf;
        #pragma unroll
        for (int g = 0; g < 2; g++) {
            float4 e0  = E4 [rp*3 + g];
            float4 o0  = O4 [rp*3 + g];
            float4 em0 = EM4[rp*3 + (1-g)];
            float4 om0 = OM4[rp*3 + (1-g)];
            float4 e1  = E4 [(rp+128)*3 + g];
            float4 o1  = O4 [(rp+128)*3 + g];
            float4 em1 = EM4[(rp+128)*3 + (1-g)];
            float4 om1 = OM4[(rp+128)*3 + (1-g)];
            const float ev0[4]  = {e0.x,  e0.y,  e0.z,  e0.w};
            const float ov0[4]  = {o0.x,  o0.y,  o0.z,  o0.w};
            const float emv0[4] = {em0.x, em0.y, em0.z, em0.w};
            const float omv0[4] = {om0.x, om0.y, om0.z, om0.w};
            const float ev1[4]  = {e1.x,  e1.y,  e1.z,  e1.w};
            const float ov1[4]  = {o1.x,  o1.y,  o1.z,  o1.w};
            const float emv1[4] = {em1.x, em1.y, em1.z, em1.w};
            const float omv1[4] = {om1.x, om1.y, om1.z, om1.w};
            const int tb = (8*c + 4*g)*10 + kyh*5;
            #pragma unroll
            for (int jj = 0; jj < 4; jj++) {
                const float se0 = ev0[jj] + emv0[3-jj];
                const float de0 = ev0[jj] - emv0[3-jj];
                const float so0 = ov0[jj] + omv0[3-jj];
                const float do0 = ov0[jj] - omv0[3-jj];
                const float se1 = ev1[jj] + emv1[3-jj];
                const float de1 = ev1[jj] - emv1[3-jj];
                const float so1 = ov1[jj] + omv1[3-jj];
                const float do1 = ov1[jj] - omv1[3-jj];
                #pragma unroll
                for (int k = 0; k < 5; k++) {
                    float4 tv = tw4[tb + jj*10 + k];   // broadcast
                    acc0[k].x = fmaf( se0, tv.x, acc0[k].x);
                    acc0[k].y = fmaf(-de0, tv.y, acc0[k].y);
                    acc0[k].z = fmaf( do0, tv.z, acc0[k].z);
                    acc0[k].w = fmaf(-so0, tv.w, acc0[k].w);
                    acc1[k].x = fmaf( se1, tv.x, acc1[k].x);
                    acc1[k].y = fmaf(-de1, tv.y, acc1[k].y);
                    acc1[k].z = fmaf( do1, tv.z, acc1[k].z);
                    acc1[k].w = fmaf(-so1, tv.w, acc1[k].w);
                }
            }
        }
    }

    __syncthreads();
    #pragma unroll
    for (int k = 0; k < 5; k++) {
        const int idx = rp*11 + kyh*5 + k;
        Xs4[idx] = make_float4(acc0[k].x + acc1[k].x, acc0[k].y + acc1[k].y,
                               acc0[k].z + acc1[k].z, acc0[k].w + acc1[k].w);
        Xd4[idx] = make_float4(acc0[k].x - acc1[k].x, acc0[k].y - acc1[k].y,
                               acc0[k].z - acc1[k].z, acc0[k].w - acc1[k].w);
    }
    __syncthreads();

    if (t < 210) {
        const int pr = t / 10;                      // 0..20
        const int kp = t % 10;

        if (pr == 0) {
            const float4* Xp = Xs4;
            float4 acc = make_float4(0.f, 0.f, 0.f, 0.f);
            #pragma unroll 8
            for (int h = 0; h < 128; h++) {
                float4 xv = Xp[h*11 + kp];
                acc.x += xv.x; acc.y += xv.y; acc.z += xv.z; acc.w += xv.w;
            }
            const int m0 = 2*kp;
            g_Xf[(size_t)m0     * NBI + bi] = make_float2(acc.x, acc.y);
            g_Xf[(size_t)(m0+1) * NBI + bi] = make_float2(acc.z, acc.w);
        } else if (pr == 20) {
            const float4* Xp = Xs4;                 // kx=236 even parity
            float4 acc = make_float4(0.f, 0.f, 0.f, 0.f);
            int p = 0;
            #pragma unroll 8
            for (int h = 0; h < 128; h++) {
                float2 e  = eb[p];
                p = (p + 236) & 255;
                float4 xv = Xp[h*11 + kp];
                acc.x = fmaf(xv.x, e.x, acc.x); acc.x = fmaf( xv.y, e.y, acc.x);
                acc.y = fmaf(xv.y, e.x, acc.y); acc.y = fmaf(-xv.x, e.y, acc.y);
                acc.z = fmaf(xv.z, e.x, acc.z); acc.z = fmaf( xv.w, e.y, acc.z);
                acc.w = fmaf(xv.w, e.x, acc.w); acc.w = fmaf(-xv.z, e.y, acc.w);
            }
            const int m0 = 20*20 + 2*kp;
            g_Xf[(size_t)m0     * NBI + bi] = make_float2(acc.x, acc.y);
            g_Xf[(size_t)(m0+1) * NBI + bi] = make_float2(acc.z, acc.w);
        } else {
            const float4* Xp = (pr & 1) ? Xd4 : Xs4;
            float4 aP = make_float4(0.f, 0.f, 0.f, 0.f);
            float4 aM = make_float4(0.f, 0.f, 0.f, 0.f);
            int p = 0;
            #pragma unroll 4
            for (int h = 0; h < 128; h++) {
                float2 e  = eb[p];
                p = (p + pr) & 255;
                float4 xv = Xp[h*11 + kp];
                aP.x = fmaf(xv.x, e.x, aP.x); aP.x = fmaf( xv.y, e.y, aP.x);
                aP.y = fmaf(xv.y, e.x, aP.y); aP.y = fmaf(-xv.x, e.y, aP.y);
                aP.z = fmaf(xv.z, e.x, aP.z); aP.z = fmaf( xv.w, e.y, aP.z);
                aP.w = fmaf(xv.w, e.x, aP.w); aP.w = fmaf(-xv.z, e.y, aP.w);
                aM.x = fmaf(xv.x, e.x, aM.x); aM.x = fmaf(-xv.y, e.y, aM.x);
                aM.y = fmaf(xv.y, e.x, aM.y); aM.y = fmaf( xv.x, e.y, aM.y);
                aM.z = fmaf(xv.z, e.x, aM.z); aM.z = fmaf(-xv.w, e.y, aM.z);
                aM.w = fmaf(xv.w, e.x, aM.w); aM.w = fmaf( xv.z, e.y, aM.w);
            }
            const int mP = pr*20 + 2*kp;
            const int mM = (40 - pr)*20 + 2*kp;
            g_Xf[(size_t)mP     * NBI + bi] = make_float2(aP.x, aP.y);
            g_Xf[(size_t)(mP+1) * NBI + bi] = make_float2(aP.z, aP.w);
            g_Xf[(size_t)mM     * NBI + bi] = make_float2(aM.x, aM.y);
            g_Xf[(size_t)(mM+1) * NBI + bi] = make_float2(aM.z, aM.w);
        }
    }
}

// ---------------------------------------------------------------------------
// Stage 3: channel mix, 2 modes per block. (unchanged)
// ---------------------------------------------------------------------------
__global__ void __launch_bounds__(256) stage3_mix(const float* __restrict__ w1re,
                                                 const float* __restrict__ w1im,
                                                 const float* __restrict__ w2re,
                                                 const float* __restrict__ w2im) {
    extern __shared__ float smem3[];
    float4* Ws  = (float4*)smem3;                 // [4096]
    float2* Xs0 = (float2*)(smem3 + 16384);       // [1024]
    float2* Xs1 = (float2*)(smem3 + 18432);       // [1024]

    const int bq  = blockIdx.x;                   // 0..399
    const int t   = threadIdx.x;
    const int j   = bq / 10;
    const int kyg = bq % 10;
    const int m0  = j*20 + 2*kyg;

    const float* wre; const float* wim; int off;
    if (j < 20) { wre = w1re; wim = w1im; off = j*20 + 2*kyg; }
    else        { wre = w2re; wim = w2im; off = (j-20)*20 + 2*kyg; }

    for (int io = t; io < 4096; io += 256) {
        float2 r2 = *(const float2*)(wre + (size_t)io*400 + off);
        float2 i2 = *(const float2*)(wim + (size_t)io*400 + off);
        Ws[io] = make_float4(r2.x, i2.x, r2.y, i2.y);
    }
    for (int i = t; i < 1024; i += 256) {
        Xs0[i] = g_Xf[(size_t)m0     * NBI + i];
        Xs1[i] = g_Xf[(size_t)(m0+1) * NBI + i];
    }
    __syncthreads();

    const int o  = t & 63;
    const int xb = (t >> 6) << 6;
    float a0R[4], a0I[4], a1R[4], a1I[4];
    #pragma unroll
    for (int k = 0; k < 4; k++) { a0R[k]=0.f; a0I[k]=0.f; a1R[k]=0.f; a1I[k]=0.f; }

    #pragma unroll 4
    for (int i = 0; i < 64; i++) {
        float4 wv = Ws[i*64 + o];
        #pragma unroll
        for (int k = 0; k < 4; k++) {
            float2 x0 = Xs0[xb + k*256 + i];
            a0R[k] = fmaf(x0.x, wv.x, a0R[k]); a0R[k] = fmaf(-x0.y, wv.y, a0R[k]);
            a0I[k] = fmaf(x0.x, wv.y, a0I[k]); a0I[k] = fmaf( x0.y, wv.x, a0I[k]);
            float2 x1 = Xs1[xb + k*256 + i];
            a1R[k] = fmaf(x1.x, wv.z, a1R[k]); a1R[k] = fmaf(-x1.y, wv.w, a1R[k]);
            a1I[k] = fmaf(x1.x, wv.w, a1I[k]); a1I[k] = fmaf( x1.y, wv.z, a1I[k]);
        }
    }
    float4* Y4 = (float4*)g_Yf;
    #pragma unroll
    for (int k = 0; k < 4; k++) {
        size_t base = ((size_t)(t + k*256) * NMODE + m0) >> 1;
        Y4[base] = make_float4(a0R[k], a0I[k], a1R[k], a1I[k]);
    }
}

// ---------------------------------------------------------------------------
// Kernel B: fused inverse H-DFT + c2r. 256 threads, 3 CTA/SM.
// Phase A: conjugate-pair blocked (as R12).
// Phase B (NEW): w-reflection split. Per (r, w in 1..32) 12 sub-accumulators
//   (even ky classes: CA,SB; odd classes: CA,SB,SA,CB) from the same 60 FMA
//   yield 8 outputs: {w+64q} and {64q-w}. w=32 self-mirrors (benign double
//   store of equal values). Columns = 0 mod 64 come from an add-only tail.
// ---------------------------------------------------------------------------
__global__ void __launch_bounds__(256, 3) stage45_bwd(float* __restrict__ out) {
    extern __shared__ float smemb[];
    float2* Yfs = (float2*)smemb;                  // [800] raw (dead after prep)
    float2* Ys  = (float2*)smemb;                  // [256][20]
    float4* SD4 = (float4*)(smemb + 10240);        // [380]
    float2* j0r = (float2*)(smemb + 11760);        // [20]
    float2* j20r= (float2*)(smemb + 11800);        // [20]
    float2* eb  = (float2*)(smemb + 11840);        // [256]

    const int bo = blockIdx.x;
    const int t  = threadIdx.x;

    for (int i = t; i < NMODE; i += 256) Yfs[i] = g_Yf[(size_t)bo * NMODE + i];
    {
        float s, c;
        sincospif((float)t * (1.0f/128.0f), &s, &c);
        eb[t] = make_float2(c, s);
    }
    __syncthreads();

    for (int i = t; i < 380; i += 256) {
        int pr = i / 20 + 1;
        int ky = i % 20;
        float2 Yp = Yfs[pr*20 + ky];
        float2 Ym = Yfs[(40 - pr)*20 + ky];
        SD4[i] = make_float4(Yp.x + Ym.x, Yp.y + Ym.y, Yp.x - Ym.x, Yp.y - Ym.y);
    }
    if (t < 20) { j0r[t] = Yfs[t]; j20r[t] = Yfs[400 + t]; }
    __syncthreads();

    // Phase A (unchanged from R12)
    {
        const int hh     = t & 127;
        const int kybase = (t >> 7) * 10;

        float aER[10], aEI[10], aOR[10], aOI[10];
        #pragma unroll
        for (int k = 0; k < 10; k++) {
            float2 y0 = j0r[kybase + k];
            aER[k] = y0.x; aEI[k] = y0.y;
            aOR[k] = 0.f;  aOI[k] = 0.f;
        }

        #pragma unroll 2
        for (int pp = 0; pp < 10; pp++) {
            const int pr = 2*pp + 1;
            float2 e = eb[(pr * hh) & 255];
            const float4* SDp = SD4 + (pr - 1)*20 + kybase;
            #pragma unroll
            for (int k = 0; k < 10; k++) {
                float4 f = SDp[k];
                aOR[k] = fmaf(f.x, e.x, aOR[k]); aOR[k] = fmaf(-f.w, e.y, aOR[k]);
                aOI[k] = fmaf(f.z, e.y, aOI[k]); aOI[k] = fmaf( f.y, e.x, aOI[k]);
            }
        }
        #pragma unroll 2
        for (int pp = 1; pp <= 9; pp++) {
            const int pr = 2*pp;
            float2 e = eb[(pr * hh) & 255];
            const float4* SDp = SD4 + (pr - 1)*20 + kybase;
            #pragma unroll
            for (int k = 0; k < 10; k++) {
                float4 f = SDp[k];
                aER[k] = fmaf(f.x, e.x, aER[k]); aER[k] = fmaf(-f.w, e.y, aER[k]);
                aEI[k] = fmaf(f.z, e.y, aEI[k]); aEI[k] = fmaf( f.y, e.x, aEI[k]);
            }
        }
        {
            float2 e = eb[(236 * hh) & 255];
            #pragma unroll
            for (int k = 0; k < 10; k++) {
                float2 y = j20r[kybase + k];
                aER[k] = fmaf(y.x, e.x, aER[k]); aER[k] = fmaf(-y.y, e.y, aER[k]);
                aEI[k] = fmaf(y.x, e.y, aEI[k]); aEI[k] = fmaf( y.y, e.x, aEI[k]);
            }
        }

        const float sc1 = 1.0f / 65536.0f;
        const float sc2 = 2.0f / 65536.0f;
        #pragma unroll
        for (int k = 0; k < 10; k++) {
            int ky  = kybase + k;
            float s = (ky == 0) ? sc1 : sc2;
            Ys[ hh       *20 + ky] = make_float2((aER[k] + aOR[k])*s, (aEI[k] + aOI[k])*s);
            Ys[(hh + 128)*20 + ky] = make_float2((aER[k] - aOR[k])*s, (aEI[k] - aOI[k])*s);
        }
        __syncthreads();
    }

    // Phase B: reflection-split c2r
    {
        const int lane = t & 31;
        const int w    = lane + 1;          // 1..32
        const int qr   = t >> 5;            // 0..7 -> rows qr*32..qr*32+31

        float cc[20], ss[20];
        #pragma unroll
        for (int ky = 0; ky < 20; ky++) {
            float s, c;
            sincospif((float)(ky * w) * (1.0f/128.0f), &s, &c);
            cc[ky] = c; ss[ky] = s;
        }

        float* outb = out + (size_t)bo * (HH*WW);
        const float4* y4 = (const float4*)Ys;

        #pragma unroll 2
        for (int rr = 0; rr < 32; rr++) {
            const int r = qr*32 + rr;
            float c0=0.f,s0=0.f,c2=0.f,s2=0.f;
            float ca1=0.f,sb1=0.f,sa1=0.f,cb1=0.f;
            float ca3=0.f,sb3=0.f,sa3=0.f,cb3=0.f;
            #pragma unroll
            for (int qq = 0; qq < 5; qq++) {
                float4 a = y4[r*10 + 2*qq];          // ky pair (4qq, 4qq+1)
                const int k0 = 4*qq, k1 = k0 + 1;
                c0  = fmaf(a.x, cc[k0], c0);
                s0  = fmaf(a.y, ss[k0], s0);
                ca1 = fmaf(a.z, cc[k1], ca1);
                sb1 = fmaf(a.w, ss[k1], sb1);
                sa1 = fmaf(a.z, ss[k1], sa1);
                cb1 = fmaf(a.w, cc[k1], cb1);
                float4 b = y4[r*10 + 2*qq + 1];      // ky pair (4qq+2, 4qq+3)
                const int k2 = k0 + 2, k3 = k0 + 3;
                c2  = fmaf(b.x, cc[k2], c2);
                s2  = fmaf(b.y, ss[k2], s2);
                ca3 = fmaf(b.z, cc[k3], ca3);
                sb3 = fmaf(b.w, ss[k3], sb3);
                sa3 = fmaf(b.z, ss[k3], sa3);
                cb3 = fmaf(b.w, cc[k3], cb3);
            }
            const float U0 = c0 - s0,  U0p = c0 + s0;
            const float U2 = c2 - s2,  U2p = c2 + s2;
            const float U1 = ca1 - sb1, U1p = ca1 + sb1;
            const float V1 = sa1 + cb1, V1p = sa1 - cb1;
            const float U3 = ca3 - sb3, U3p = ca3 + sb3;
            const float V3 = sa3 + cb3, V3p = sa3 - cb3;
            float* ro = outb + r*256;
            ro[w      ] = U0 + U1 + U2 + U3;
            ro[w + 64 ] = U0 - V1 - U2 + V3;
            ro[w + 128] = U0 - U1 + U2 - U3;
            ro[w + 192] = U0 + V1 - U2 - V3;
            ro[64  - w] = U0p + V1p - U2p - V3p;
            ro[128 - w] = U0p - U1p + U2p - U3p;
            ro[192 - w] = U0p - V1p - U2p + V3p;
            ro[256 - w] = U0p + U1p + U2p + U3p;
        }

        // tail: columns {0,64,128,192}, one row per thread, adds only
        {
            const int r = t;
            float R0=0.f,R1=0.f,R2=0.f,R3=0.f,I1=0.f,I3=0.f;
            #pragma unroll
            for (int qq = 0; qq < 5; qq++) {
                float4 a = y4[r*10 + 2*qq];
                R0 += a.x; R1 += a.z; I1 += a.w;
                float4 b = y4[r*10 + 2*qq + 1];
                R2 += b.x; R3 += b.z; I3 += b.w;
            }
            float* ro = outb + r*256;
            ro[0  ] = R0 + R1 + R2 + R3;
            ro[64 ] = R0 - I1 - R2 + I3;
            ro[128] = R0 - R1 + R2 - R3;
            ro[192] = R0 + I1 - R2 - I3;
        }
    }
}

// ---------------------------------------------------------------------------
extern "C" void kernel_launch(void* const* d_in, const int* in_sizes, int n_in,
                              void* d_out, int out_size) {
    const float* x    = (const float*)d_in[0];
    const float* w1re = (const float*)d_in[1];
    const float* w1im = (const float*)d_in[2];
    const float* w2re = (const float*)d_in[3];
    const float* w2im = (const float*)d_in[4];
    float* out = (float*)d_out;

    const int sA = 61440;
    const int s3 = 81920;
    const int sB = 49408;
    cudaFuncSetAttribute(stage12_fwd, cudaFuncAttributeMaxDynamicSharedMemorySize, sA);
    cudaFuncSetAttribute(stage3_mix,  cudaFuncAttributeMaxDynamicSharedMemorySize, s3);
    cudaFuncSetAttribute(stage45_bwd, cudaFuncAttributeMaxDynamicSharedMemorySize, sB);

    stage12_fwd<<<NBI, 256, sA>>>(x);
    stage3_mix <<<400, 256, s3>>>(w1re, w1im, w2re, w2im);
    stage45_bwd<<<NBO, 256, sB>>>(out);
}

// round 14
// speedup vs baseline: 1.0625x; 1.0625x over previous
#include <cuda_runtime.h>
#include <math.h>

#define BB   16
#define CIN  64
#define COUT 64
#define HH   256
#define WW   256
#define NMODE 800        // 40 kx * 20 ky
#define NBI  1024        // B*CI
#define NBO  1024        // B*CO

__device__ float2 g_Xf[NMODE * NBI];       // [m][bi]  6.6 MB
__device__ float2 g_Yf[NBO * NMODE];       // [bo][m]  6.6 MB

// ---------------------------------------------------------------------------
// Kernel A: fused W-DFT + H-DFT for one (b,ci) image. 256 threads, 2 CTA/SM.
// (R8/R12 configuration: best measured 132.7 us. Unchanged.)
// ---------------------------------------------------------------------------
__global__ void __launch_bounds__(256, 2) stage12_fwd(const float* __restrict__ x) {
    extern __shared__ float smem[];
    float*  Ef  = smem;                            // [256*12]
    float*  Of  = smem + 3072;
    float*  EMf = smem + 6144;
    float*  OMf = smem + 9216;
    float4* tw4 = (float4*)(smem + 12288);         // [64][10]
    float2* eb  = (float2*)(smem + 14848);         // [256]
    float4* Xs4 = (float4*)smem;                   // [128][11] (phase-2 input)
    float4* Xd4 = Xs4 + 1408;

    const int bi  = blockIdx.x;
    const int t   = threadIdx.x;
    const int rp  = t & 127;
    const int kyh = t >> 7;                        // warp-uniform ky half

    for (int i = t; i < 640; i += 256) {
        int wi = i / 10 + 1, kk = i % 10;
        float s0, c0, s1, c1;
        sincospif((float)((2*kk    ) * wi) * (1.0f/128.0f), &s0, &c0);
        sincospif((float)((2*kk + 1) * wi) * (1.0f/128.0f), &s1, &c1);
        float hsc = (wi == 64) ? 0.5f : 1.0f;
        tw4[i] = make_float4(c0*hsc, s0*hsc, c1*hsc, s1*hsc);
    }
    {
        float s, c;
        sincospif((float)t * (1.0f/128.0f), &s, &c);
        eb[t] = make_float2(c, s);
    }

    const float* img = x + (size_t)bi * (HH*WW);

    float4 acc0[5], acc1[5];
    {
        float a0 = img[rp*WW],         b0 = img[rp*WW + 128];
        float a1 = img[(rp+128)*WW],   b1 = img[(rp+128)*WW + 128];
        float ue0 = a0 + b0, uo0 = a0 - b0;
        float ue1 = a1 + b1, uo1 = a1 - b1;
        #pragma unroll
        for (int k = 0; k < 5; k++) {
            acc0[k] = make_float4(ue0, 0.f, uo0, 0.f);   // w=0 term (c=1,s=0)
            acc1[k] = make_float4(ue1, 0.f, uo1, 0.f);
        }
    }

    for (int c = 0; c < 8; c++) {                  // chunks of 8 w, w = 1..64
        const int w0     = 1 + 8*c;
        const int mstart = 120 - 8*c;              // mirror window start
        __syncthreads();
        #pragma unroll
        for (int i = 0; i < 8; i++) {
            int idx = t + i*256;                   // 0..2047
            int r   = idx >> 3;
            int j   = idx & 7;
            const float* rpn = img + r * WW;
            float a1 = rpn[w0 + j],     b1 = rpn[w0 + j + 128];
            float a2 = rpn[mstart + j], b2 = rpn[mstart + j + 128];
            int s = r*12 + j;
            Ef[s]  = a1 + b1;  Of[s]  = a1 - b1;
            EMf[s] = a2 + b2;  OMf[s] = a2 - b2;
        }
        __syncthreads();

        const float4* E4  = (const float4*)Ef;
        const float4* O4  = (const float4*)Of;
        const float4* EM4 = (const float4*)EMf;
        const float4* OM4 = (const float4*)OMf;
        #pragma unroll
        for (int g = 0; g < 2; g++) {
            float4 e0  = E4 [rp*3 + g];
            float4 o0  = O4 [rp*3 + g];
            float4 em0 = EM4[rp*3 + (1-g)];
            float4 om0 = OM4[rp*3 + (1-g)];
            float4 e1  = E4 [(rp+128)*3 + g];
            float4 o1  = O4 [(rp+128)*3 + g];
            float4 em1 = EM4[(rp+128)*3 + (1-g)];
            float4 om1 = OM4[(rp+128)*3 + (1-g)];
            const float ev0[4]  = {e0.x,  e0.y,  e0.z,  e0.w};
            const float ov0[4]  = {o0.x,  o0.y,  o0.z,  o0.w};
            const float emv0[4] = {em0.x, em0.y, em0.z, em0.w};
            const float omv0[4] = {om0.x, om0.y, om0.z, om0.w};
            const float ev1[4]  = {e1.x,  e1.y,  e1.z,  e1.w};
            const float ov1[4]  = {o1.x,  o1.y,  o1.z,  o1.w};
            const float emv1[4] = {em1.x, em1.y, em1.z, em1.w};
            const float omv1[4] = {om1.x, om1.y, om1.z, om1.w};
            const int tb = (8*c + 4*g)*10 + kyh*5;
            #pragma unroll
            for (int jj = 0; jj < 4; jj++) {
                const float se0 = ev0[jj] + emv0[3-jj];
                const float de0 = ev0[jj] - emv0[3-jj];
                const float so0 = ov0[jj] + omv0[3-jj];
                const float do0 = ov0[jj] - omv0[3-jj];
                const float se1 = ev1[jj] + emv1[3-jj];
                const float de1 = ev1[jj] - emv1[3-jj];
                const float so1 = ov1[jj] + omv1[3-jj];
                const float do1 = ov1[jj] - omv1[3-jj];
                #pragma unroll
                for (int k = 0; k < 5; k++) {
                    float4 tv = tw4[tb + jj*10 + k];   // broadcast
                    acc0[k].x = fmaf( se0, tv.x, acc0[k].x);
                    acc0[k].y = fmaf(-de0, tv.y, acc0[k].y);
                    acc0[k].z = fmaf( do0, tv.z, acc0[k].z);
                    acc0[k].w = fmaf(-so0, tv.w, acc0[k].w);
                    acc1[k].x = fmaf( se1, tv.x, acc1[k].x);
                    acc1[k].y = fmaf(-de1, tv.y, acc1[k].y);
                    acc1[k].z = fmaf( do1, tv.z, acc1[k].z);
                    acc1[k].w = fmaf(-so1, tv.w, acc1[k].w);
                }
            }
        }
    }

    __syncthreads();
    #pragma unroll
    for (int k = 0; k < 5; k++) {
        const int idx = rp*11 + kyh*5 + k;
        Xs4[idx] = make_float4(acc0[k].x + acc1[k].x, acc0[k].y + acc1[k].y,
                               acc0[k].z + acc1[k].z, acc0[k].w + acc1[k].w);
        Xd4[idx] = make_float4(acc0[k].x - acc1[k].x, acc0[k].y - acc1[k].y,
                               acc0[k].z - acc1[k].z, acc0[k].w - acc1[k].w);
    }
    __syncthreads();

    if (t < 210) {
        const int pr = t / 10;                      // 0..20
        const int kp = t % 10;

        if (pr == 0) {
            const float4* Xp = Xs4;
            float4 acc = make_float4(0.f, 0.f, 0.f, 0.f);
            #pragma unroll 8
            for (int h = 0; h < 128; h++) {
                float4 xv = Xp[h*11 + kp];
                acc.x += xv.x; acc.y += xv.y; acc.z += xv.z; acc.w += xv.w;
            }
            const int m0 = 2*kp;
            g_Xf[(size_t)m0     * NBI + bi] = make_float2(acc.x, acc.y);
            g_Xf[(size_t)(m0+1) * NBI + bi] = make_float2(acc.z, acc.w);
        } else if (pr == 20) {
            const float4* Xp = Xs4;                 // kx=236 even parity
            float4 acc = make_float4(0.f, 0.f, 0.f, 0.f);
            int p = 0;
            #pragma unroll 8
            for (int h = 0; h < 128; h++) {
                float2 e  = eb[p];
                p = (p + 236) & 255;
                float4 xv = Xp[h*11 + kp];
                acc.x = fmaf(xv.x, e.x, acc.x); acc.x = fmaf( xv.y, e.y, acc.x);
                acc.y = fmaf(xv.y, e.x, acc.y); acc.y = fmaf(-xv.x, e.y, acc.y);
                acc.z = fmaf(xv.z, e.x, acc.z); acc.z = fmaf( xv.w, e.y, acc.z);
                acc.w = fmaf(xv.w, e.x, acc.w); acc.w = fmaf(-xv.z, e.y, acc.w);
            }
            const int m0 = 20*20 + 2*kp;
            g_Xf[(size_t)m0     * NBI + bi] = make_float2(acc.x, acc.y);
            g_Xf[(size_t)(m0+1) * NBI + bi] = make_float2(acc.z, acc.w);
        } else {
            const float4* Xp = (pr & 1) ? Xd4 : Xs4;
            float4 aP = make_float4(0.f, 0.f, 0.f, 0.f);
            float4 aM = make_float4(0.f, 0.f, 0.f, 0.f);
            int p = 0;
            #pragma unroll 4
            for (int h = 0; h < 128; h++) {
                float2 e  = eb[p];
                p = (p + pr) & 255;
                float4 xv = Xp[h*11 + kp];
                aP.x = fmaf(xv.x, e.x, aP.x); aP.x = fmaf( xv.y, e.y, aP.x);
                aP.y = fmaf(xv.y, e.x, aP.y); aP.y = fmaf(-xv.x, e.y, aP.y);
                aP.z = fmaf(xv.z, e.x, aP.z); aP.z = fmaf( xv.w, e.y, aP.z);
                aP.w = fmaf(xv.w, e.x, aP.w); aP.w = fmaf(-xv.z, e.y, aP.w);
                aM.x = fmaf(xv.x, e.x, aM.x); aM.x = fmaf(-xv.y, e.y, aM.x);
                aM.y = fmaf(xv.y, e.x, aM.y); aM.y = fmaf( xv.x, e.y, aM.y);
                aM.z = fmaf(xv.z, e.x, aM.z); aM.z = fmaf(-xv.w, e.y, aM.z);
                aM.w = fmaf(xv.w, e.x, aM.w); aM.w = fmaf( xv.z, e.y, aM.w);
            }
            const int mP = pr*20 + 2*kp;
            const int mM = (40 - pr)*20 + 2*kp;
            g_Xf[(size_t)mP     * NBI + bi] = make_float2(aP.x, aP.y);
            g_Xf[(size_t)(mP+1) * NBI + bi] = make_float2(aP.z, aP.w);
            g_Xf[(size_t)mM     * NBI + bi] = make_float2(aM.x, aM.y);
            g_Xf[(size_t)(mM+1) * NBI + bi] = make_float2(aM.z, aM.w);
        }
    }
}

// ---------------------------------------------------------------------------
// Stage 3: channel mix, 2 modes per block. (unchanged)
// ---------------------------------------------------------------------------
__global__ void __launch_bounds__(256) stage3_mix(const float* __restrict__ w1re,
                                                 const float* __restrict__ w1im,
                                                 const float* __restrict__ w2re,
                                                 const float* __restrict__ w2im) {
    extern __shared__ float smem3[];
    float4* Ws  = (float4*)smem3;                 // [4096]
    float2* Xs0 = (float2*)(smem3 + 16384);       // [1024]
    float2* Xs1 = (float2*)(smem3 + 18432);       // [1024]

    const int bq  = blockIdx.x;                   // 0..399
    const int t   = threadIdx.x;
    const int j   = bq / 10;
    const int kyg = bq % 10;
    const int m0  = j*20 + 2*kyg;

    const float* wre; const float* wim; int off;
    if (j < 20) { wre = w1re; wim = w1im; off = j*20 + 2*kyg; }
    else        { wre = w2re; wim = w2im; off = (j-20)*20 + 2*kyg; }

    for (int io = t; io < 4096; io += 256) {
        float2 r2 = *(const float2*)(wre + (size_t)io*400 + off);
        float2 i2 = *(const float2*)(wim + (size_t)io*400 + off);
        Ws[io] = make_float4(r2.x, i2.x, r2.y, i2.y);
    }
    for (int i = t; i < 1024; i += 256) {
        Xs0[i] = g_Xf[(size_t)m0     * NBI + i];
        Xs1[i] = g_Xf[(size_t)(m0+1) * NBI + i];
    }
    __syncthreads();

    const int o  = t & 63;
    const int xb = (t >> 6) << 6;
    float a0R[4], a0I[4], a1R[4], a1I[4];
    #pragma unroll
    for (int k = 0; k < 4; k++) { a0R[k]=0.f; a0I[k]=0.f; a1R[k]=0.f; a1I[k]=0.f; }

    #pragma unroll 4
    for (int i = 0; i < 64; i++) {
        float4 wv = Ws[i*64 + o];
        #pragma unroll
        for (int k = 0; k < 4; k++) {
            float2 x0 = Xs0[xb + k*256 + i];
            a0R[k] = fmaf(x0.x, wv.x, a0R[k]); a0R[k] = fmaf(-x0.y, wv.y, a0R[k]);
            a0I[k] = fmaf(x0.x, wv.y, a0I[k]); a0I[k] = fmaf( x0.y, wv.x, a0I[k]);
            float2 x1 = Xs1[xb + k*256 + i];
            a1R[k] = fmaf(x1.x, wv.z, a1R[k]); a1R[k] = fmaf(-x1.y, wv.w, a1R[k]);
            a1I[k] = fmaf(x1.x, wv.w, a1I[k]); a1I[k] = fmaf( x1.y, wv.z, a1I[k]);
        }
    }
    float4* Y4 = (float4*)g_Yf;
    #pragma unroll
    for (int k = 0; k < 4; k++) {
        size_t base = ((size_t)(t + k*256) * NMODE + m0) >> 1;
        Y4[base] = make_float4(a0R[k], a0I[k], a1R[k], a1I[k]);
    }
}

// ---------------------------------------------------------------------------
// Kernel B: fused inverse H-DFT + c2r. 256 threads, 2 CTA/SM (128 regs: the
// reflection-split phase B needs ~75 live regs; the R13 84-reg cap spilled).
// Phase A: conjugate-pair blocked (as R12).
// Phase B: w-reflection split — 60 FMA per (r,w) produce 8 outputs.
// ---------------------------------------------------------------------------
__global__ void __launch_bounds__(256, 2) stage45_bwd(float* __restrict__ out) {
    extern __shared__ float smemb[];
    float2* Yfs = (float2*)smemb;                  // [800] raw (dead after prep)
    float2* Ys  = (float2*)smemb;                  // [256][20]
    float4* SD4 = (float4*)(smemb + 10240);        // [380]
    float2* j0r = (float2*)(smemb + 11760);        // [20]
    float2* j20r= (float2*)(smemb + 11800);        // [20]
    float2* eb  = (float2*)(smemb + 11840);        // [256]

    const int bo = blockIdx.x;
    const int t  = threadIdx.x;

    for (int i = t; i < NMODE; i += 256) Yfs[i] = g_Yf[(size_t)bo * NMODE + i];
    {
        float s, c;
        sincospif((float)t * (1.0f/128.0f), &s, &c);
        eb[t] = make_float2(c, s);
    }
    __syncthreads();

    for (int i = t; i < 380; i += 256) {
        int pr = i / 20 + 1;
        int ky = i % 20;
        float2 Yp = Yfs[pr*20 + ky];
        float2 Ym = Yfs[(40 - pr)*20 + ky];
        SD4[i] = make_float4(Yp.x + Ym.x, Yp.y + Ym.y, Yp.x - Ym.x, Yp.y - Ym.y);
    }
    if (t < 20) { j0r[t] = Yfs[t]; j20r[t] = Yfs[400 + t]; }
    __syncthreads();

    // Phase A (unchanged from R12)
    {
        const int hh     = t & 127;
        const int kybase = (t >> 7) * 10;

        float aER[10], aEI[10], aOR[10], aOI[10];
        #pragma unroll
        for (int k = 0; k < 10; k++) {
            float2 y0 = j0r[kybase + k];
            aER[k] = y0.x; aEI[k] = y0.y;
            aOR[k] = 0.f;  aOI[k] = 0.f;
        }

        #pragma unroll 2
        for (int pp = 0; pp < 10; pp++) {
            const int pr = 2*pp + 1;
            float2 e = eb[(pr * hh) & 255];
            const float4* SDp = SD4 + (pr - 1)*20 + kybase;
            #pragma unroll
            for (int k = 0; k < 10; k++) {
                float4 f = SDp[k];
                aOR[k] = fmaf(f.x, e.x, aOR[k]); aOR[k] = fmaf(-f.w, e.y, aOR[k]);
                aOI[k] = fmaf(f.z, e.y, aOI[k]); aOI[k] = fmaf( f.y, e.x, aOI[k]);
            }
        }
        #pragma unroll 2
        for (int pp = 1; pp <= 9; pp++) {
            const int pr = 2*pp;
            float2 e = eb[(pr * hh) & 255];
            const float4* SDp = SD4 + (pr - 1)*20 + kybase;
            #pragma unroll
            for (int k = 0; k < 10; k++) {
                float4 f = SDp[k];
                aER[k] = fmaf(f.x, e.x, aER[k]); aER[k] = fmaf(-f.w, e.y, aER[k]);
                aEI[k] = fmaf(f.z, e.y, aEI[k]); aEI[k] = fmaf( f.y, e.x, aEI[k]);
            }
        }
        {
            float2 e = eb[(236 * hh) & 255];
            #pragma unroll
            for (int k = 0; k < 10; k++) {
                float2 y = j20r[kybase + k];
                aER[k] = fmaf(y.x, e.x, aER[k]); aER[k] = fmaf(-y.y, e.y, aER[k]);
                aEI[k] = fmaf(y.x, e.y, aEI[k]); aEI[k] = fmaf( y.y, e.x, aEI[k]);
            }
        }

        const float sc1 = 1.0f / 65536.0f;
        const float sc2 = 2.0f / 65536.0f;
        #pragma unroll
        for (int k = 0; k < 10; k++) {
            int ky  = kybase + k;
            float s = (ky == 0) ? sc1 : sc2;
            Ys[ hh       *20 + ky] = make_float2((aER[k] + aOR[k])*s, (aEI[k] + aOI[k])*s);
            Ys[(hh + 128)*20 + ky] = make_float2((aER[k] - aOR[k])*s, (aEI[k] - aOI[k])*s);
        }
        __syncthreads();
    }

    // Phase B: reflection-split c2r
    {
        const int lane = t & 31;
        const int w    = lane + 1;          // 1..32
        const int qr   = t >> 5;            // 0..7 -> rows qr*32..qr*32+31

        float cc[20], ss[20];
        #pragma unroll
        for (int ky = 0; ky < 20; ky++) {
            float s, c;
            sincospif((float)(ky * w) * (1.0f/128.0f), &s, &c);
            cc[ky] = c; ss[ky] = s;
        }

        float* outb = out + (size_t)bo * (HH*WW);
        const float4* y4 = (const float4*)Ys;

        #pragma unroll 2
        for (int rr = 0; rr < 32; rr++) {
            const int r = qr*32 + rr;
            float c0=0.f,s0=0.f,c2=0.f,s2=0.f;
            float ca1=0.f,sb1=0.f,sa1=0.f,cb1=0.f;
            float ca3=0.f,sb3=0.f,sa3=0.f,cb3=0.f;
            #pragma unroll
            for (int qq = 0; qq < 5; qq++) {
                float4 a = y4[r*10 + 2*qq];          // ky pair (4qq, 4qq+1)
                const int k0 = 4*qq, k1 = k0 + 1;
                c0  = fmaf(a.x, cc[k0], c0);
                s0  = fmaf(a.y, ss[k0], s0);
                ca1 = fmaf(a.z, cc[k1], ca1);
                sb1 = fmaf(a.w, ss[k1], sb1);
                sa1 = fmaf(a.z, ss[k1], sa1);
                cb1 = fmaf(a.w, cc[k1], cb1);
                float4 b = y4[r*10 + 2*qq + 1];      // ky pair (4qq+2, 4qq+3)
                const int k2 = k0 + 2, k3 = k0 + 3;
                c2  = fmaf(b.x, cc[k2], c2);
                s2  = fmaf(b.y, ss[k2], s2);
                ca3 = fmaf(b.z, cc[k3], ca3);
                sb3 = fmaf(b.w, ss[k3], sb3);
                sa3 = fmaf(b.z, ss[k3], sa3);
                cb3 = fmaf(b.w, cc[k3], cb3);
            }
            const float U0 = c0 - s0,  U0p = c0 + s0;
            const float U2 = c2 - s2,  U2p = c2 + s2;
            const float U1 = ca1 - sb1, U1p = ca1 + sb1;
            const float V1 = sa1 + cb1, V1p = sa1 - cb1;
            const float U3 = ca3 - sb3, U3p = ca3 + sb3;
            const float V3 = sa3 + cb3, V3p = sa3 - cb3;
            float* ro = outb + r*256;
            ro[w      ] = U0 + U1 + U2 + U3;
            ro[w + 64 ] = U0 - V1 - U2 + V3;
            ro[w + 128] = U0 - U1 + U2 - U3;
            ro[w + 192] = U0 + V1 - U2 - V3;
            ro[64  - w] = U0p + V1p - U2p - V3p;
            ro[128 - w] = U0p - U1p + U2p - U3p;
            ro[192 - w] = U0p - V1p - U2p + V3p;
            ro[256 - w] = U0p + U1p + U2p + U3p;
        }

        // tail: columns {0,64,128,192}, one row per thread, adds only
        {
            const int r = t;
            float R0=0.f,R1=0.f,R2=0.f,R3=0.f,I1=0.f,I3=0.f;
            #pragma unroll
            for (int qq = 0; qq < 5; qq++) {
                float4 a = y4[r*10 + 2*qq];
                R0 += a.x; R1 += a.z; I1 += a.w;
                float4 b = y4[r*10 + 2*qq + 1];
                R2 += b.x; R3 += b.z; I3 += b.w;
            }
            float* ro = outb + r*256;
            ro[0  ] = R0 + R1 + R2 + R3;
            ro[64 ] = R0 - I1 - R2 + I3;
            ro[128] = R0 - R1 + R2 - R3;
            ro[192] = R0 + I1 - R2 - I3;
        }
    }
}

// ---------------------------------------------------------------------------
extern "C" void kernel_launch(void* const* d_in, const int* in_sizes, int n_in,
                              void* d_out, int out_size) {
    const float* x    = (const float*)d_in[0];
    const float* w1re = (const float*)d_in[1];
    const float* w1im = (const float*)d_in[2];
    const float* w2re = (const float*)d_in[3];
    const float* w2im = (const float*)d_in[4];
    float* out = (float*)d_out;

    const int sA = 61440;
    const int s3 = 81920;
    const int sB = 49408;
    cudaFuncSetAttribute(stage12_fwd, cudaFuncAttributeMaxDynamicSharedMemorySize, sA);
    cudaFuncSetAttribute(stage3_mix,  cudaFuncAttributeMaxDynamicSharedMemorySize, s3);
    cudaFuncSetAttribute(stage45_bwd, cudaFuncAttributeMaxDynamicSharedMemorySize, sB);

    stage12_fwd<<<NBI, 256, sA>>>(x);
    stage3_mix <<<400, 256, s3>>>(w1re, w1im, w2re, w2im);
    stage45_bwd<<<NBO, 256, sB>>>(out);
}

// round 15
// speedup vs baseline: 1.0855x; 1.0217x over previous
#include <cuda_runtime.h>
#include <math.h>

#define BB   16
#define CIN  64
#define COUT 64
#define HH   256
#define WW   256
#define NMODE 800        // 40 kx * 20 ky
#define NBI  1024        // B*CI
#define NBO  1024        // B*CO

typedef unsigned long long u64;

__device__ __forceinline__ u64 pk2(float lo, float hi) {
    u64 r; asm("mov.b64 %0, {%1,%2};" : "=l"(r) : "f"(lo), "f"(hi)); return r;
}
__device__ __forceinline__ void upk2(u64 v, float& lo, float& hi) {
    asm("mov.b64 {%0,%1}, %2;" : "=f"(lo), "=f"(hi) : "l"(v));
}
__device__ __forceinline__ u64 ffma2(u64 a, u64 b, u64 c) {
    u64 d; asm("fma.rn.f32x2 %0, %1, %2, %3;" : "=l"(d) : "l"(a), "l"(b), "l"(c)); return d;
}

__device__ float2 g_Xf[NMODE * NBI];       // [m][bi]  6.6 MB
__device__ float2 g_Yf[NBO * NMODE];       // [bo][m]  6.6 MB

// ---------------------------------------------------------------------------
// Kernel A: fused W-DFT + H-DFT. 256 threads, 2 CTA/SM.
// Phase 1 inner loop packed: tw holds (c,-s); acc pairs via fma.rn.f32x2.
// ---------------------------------------------------------------------------
__global__ void __launch_bounds__(256, 2) stage12_fwd(const float* __restrict__ x) {
    extern __shared__ float smem[];
    float*  Ef  = smem;                            // [256*12]
    float*  Of  = smem + 3072;
    float*  EMf = smem + 6144;
    float*  OMf = smem + 9216;
    float4* tw4 = (float4*)(smem + 12288);         // [64][10] (c,-s,c',-s')
    float2* eb  = (float2*)(smem + 14848);         // [256]
    float4* Xs4 = (float4*)smem;                   // [128][11] (phase-2 input)
    float4* Xd4 = Xs4 + 1408;

    const int bi  = blockIdx.x;
    const int t   = threadIdx.x;
    const int rp  = t & 127;
    const int kyh = t >> 7;                        // warp-uniform ky half

    for (int i = t; i < 640; i += 256) {
        int wi = i / 10 + 1, kk = i % 10;
        float s0, c0, s1, c1;
        sincospif((float)((2*kk    ) * wi) * (1.0f/128.0f), &s0, &c0);
        sincospif((float)((2*kk + 1) * wi) * (1.0f/128.0f), &s1, &c1);
        float hsc = (wi == 64) ? 0.5f : 1.0f;
        tw4[i] = make_float4(c0*hsc, -s0*hsc, c1*hsc, -s1*hsc);   // NOTE: -s baked in
    }
    {
        float s, c;
        sincospif((float)t * (1.0f/128.0f), &s, &c);
        eb[t] = make_float2(c, s);
    }

    const float* img = x + (size_t)bi * (HH*WW);

    // packed accumulators: xy = (Re_e, Im_e), zw = (Re_o, Im_o) per ky pair k
    u64 a0xy[5], a0zw[5], a1xy[5], a1zw[5];
    {
        float a0 = img[rp*WW],         b0 = img[rp*WW + 128];
        float a1 = img[(rp+128)*WW],   b1 = img[(rp+128)*WW + 128];
        float ue0 = a0 + b0, uo0 = a0 - b0;
        float ue1 = a1 + b1, uo1 = a1 - b1;
        #pragma unroll
        for (int k = 0; k < 5; k++) {
            a0xy[k] = pk2(ue0, 0.f);  a0zw[k] = pk2(uo0, 0.f);
            a1xy[k] = pk2(ue1, 0.f);  a1zw[k] = pk2(uo1, 0.f);
        }
    }

    for (int c = 0; c < 8; c++) {                  // chunks of 8 w, w = 1..64
        const int w0     = 1 + 8*c;
        const int mstart = 120 - 8*c;              // mirror window start
        __syncthreads();
        #pragma unroll
        for (int i = 0; i < 8; i++) {
            int idx = t + i*256;                   // 0..2047
            int r   = idx >> 3;
            int j   = idx & 7;
            const float* rpn = img + r * WW;
            float a1 = rpn[w0 + j],     b1 = rpn[w0 + j + 128];
            float a2 = rpn[mstart + j], b2 = rpn[mstart + j + 128];
            int s = r*12 + j;
            Ef[s]  = a1 + b1;  Of[s]  = a1 - b1;
            EMf[s] = a2 + b2;  OMf[s] = a2 - b2;
        }
        __syncthreads();

        const float4* E4  = (const float4*)Ef;
        const float4* O4  = (const float4*)Of;
        const float4* EM4 = (const float4*)EMf;
        const float4* OM4 = (const float4*)OMf;
        const ulonglong2* tw8 = (const ulonglong2*)tw4;
        #pragma unroll
        for (int g = 0; g < 2; g++) {
            float4 e0  = E4 [rp*3 + g];
            float4 o0  = O4 [rp*3 + g];
            float4 em0 = EM4[rp*3 + (1-g)];
            float4 om0 = OM4[rp*3 + (1-g)];
            float4 e1  = E4 [(rp+128)*3 + g];
            float4 o1  = O4 [(rp+128)*3 + g];
            float4 em1 = EM4[(rp+128)*3 + (1-g)];
            float4 om1 = OM4[(rp+128)*3 + (1-g)];
            const float ev0[4]  = {e0.x,  e0.y,  e0.z,  e0.w};
            const float ov0[4]  = {o0.x,  o0.y,  o0.z,  o0.w};
            const float emv0[4] = {em0.x, em0.y, em0.z, em0.w};
            const float omv0[4] = {om0.x, om0.y, om0.z, om0.w};
            const float ev1[4]  = {e1.x,  e1.y,  e1.z,  e1.w};
            const float ov1[4]  = {o1.x,  o1.y,  o1.z,  o1.w};
            const float emv1[4] = {em1.x, em1.y, em1.z, em1.w};
            const float omv1[4] = {om1.x, om1.y, om1.z, om1.w};
            const int tb = (8*c + 4*g)*10 + kyh*5;
            #pragma unroll
            for (int jj = 0; jj < 4; jj++) {
                const float se0 = ev0[jj] + emv0[3-jj];
                const float de0 = ev0[jj] - emv0[3-jj];
                const float so0 = ov0[jj] + omv0[3-jj];
                const float do0 = ov0[jj] - omv0[3-jj];
                const float se1 = ev1[jj] + emv1[3-jj];
                const float de1 = ev1[jj] - emv1[3-jj];
                const float so1 = ov1[jj] + omv1[3-jj];
                const float do1 = ov1[jj] - omv1[3-jj];
                u64 ed0 = pk2(se0, de0), os0 = pk2(do0, so0);
                u64 ed1 = pk2(se1, de1), os1 = pk2(do1, so1);
                #pragma unroll
                for (int k = 0; k < 5; k++) {
                    ulonglong2 tv = tw8[tb + jj*10 + k];   // broadcast (c,-s | c',-s')
                    a0xy[k] = ffma2(ed0, tv.x, a0xy[k]);
                    a0zw[k] = ffma2(os0, tv.y, a0zw[k]);
                    a1xy[k] = ffma2(ed1, tv.x, a1xy[k]);
                    a1zw[k] = ffma2(os1, tv.y, a1zw[k]);
                }
            }
        }
    }

    // h-fold in registers (rows rp / rp+128), store Xsum/Xdif at pitch 11
    __syncthreads();
    #pragma unroll
    for (int k = 0; k < 5; k++) {
        float r0e, i0e, r0o, i0o, r1e, i1e, r1o, i1o;
        upk2(a0xy[k], r0e, i0e);  upk2(a0zw[k], r0o, i0o);
        upk2(a1xy[k], r1e, i1e);  upk2(a1zw[k], r1o, i1o);
        const int idx = rp*11 + kyh*5 + k;
        Xs4[idx] = make_float4(r0e + r1e, i0e + i1e, r0o + r1o, i0o + i1o);
        Xd4[idx] = make_float4(r0e - r1e, i0e - i1e, r0o - r1o, i0o - i1o);
    }
    __syncthreads();

    // Phase 2: conjugate-pair blocked H-DFT (scalar, unchanged). 210 threads.
    if (t < 210) {
        const int pr = t / 10;                      // 0..20
        const int kp = t % 10;

        if (pr == 0) {
            const float4* Xp = Xs4;
            float4 acc = make_float4(0.f, 0.f, 0.f, 0.f);
            #pragma unroll 8
            for (int h = 0; h < 128; h++) {
                float4 xv = Xp[h*11 + kp];
                acc.x += xv.x; acc.y += xv.y; acc.z += xv.z; acc.w += xv.w;
            }
            const int m0 = 2*kp;
            g_Xf[(size_t)m0     * NBI + bi] = make_float2(acc.x, acc.y);
            g_Xf[(size_t)(m0+1) * NBI + bi] = make_float2(acc.z, acc.w);
        } else if (pr == 20) {
            const float4* Xp = Xs4;                 // kx=236 even parity
            float4 acc = make_float4(0.f, 0.f, 0.f, 0.f);
            int p = 0;
            #pragma unroll 8
            for (int h = 0; h < 128; h++) {
                float2 e  = eb[p];
                p = (p + 236) & 255;
                float4 xv = Xp[h*11 + kp];
                acc.x = fmaf(xv.x, e.x, acc.x); acc.x = fmaf( xv.y, e.y, acc.x);
                acc.y = fmaf(xv.y, e.x, acc.y); acc.y = fmaf(-xv.x, e.y, acc.y);
                acc.z = fmaf(xv.z, e.x, acc.z); acc.z = fmaf( xv.w, e.y, acc.z);
                acc.w = fmaf(xv.w, e.x, acc.w); acc.w = fmaf(-xv.z, e.y, acc.w);
            }
            const int m0 = 20*20 + 2*kp;
            g_Xf[(size_t)m0     * NBI + bi] = make_float2(acc.x, acc.y);
            g_Xf[(size_t)(m0+1) * NBI + bi] = make_float2(acc.z, acc.w);
        } else {
            const float4* Xp = (pr & 1) ? Xd4 : Xs4;
            float4 aP = make_float4(0.f, 0.f, 0.f, 0.f);
            float4 aM = make_float4(0.f, 0.f, 0.f, 0.f);
            int p = 0;
            #pragma unroll 4
            for (int h = 0; h < 128; h++) {
                float2 e  = eb[p];
                p = (p + pr) & 255;
                float4 xv = Xp[h*11 + kp];
                aP.x = fmaf(xv.x, e.x, aP.x); aP.x = fmaf( xv.y, e.y, aP.x);
                aP.y = fmaf(xv.y, e.x, aP.y); aP.y = fmaf(-xv.x, e.y, aP.y);
                aP.z = fmaf(xv.z, e.x, aP.z); aP.z = fmaf( xv.w, e.y, aP.z);
                aP.w = fmaf(xv.w, e.x, aP.w); aP.w = fmaf(-xv.z, e.y, aP.w);
                aM.x = fmaf(xv.x, e.x, aM.x); aM.x = fmaf(-xv.y, e.y, aM.x);
                aM.y = fmaf(xv.y, e.x, aM.y); aM.y = fmaf( xv.x, e.y, aM.y);
                aM.z = fmaf(xv.z, e.x, aM.z); aM.z = fmaf(-xv.w, e.y, aM.z);
                aM.w = fmaf(xv.w, e.x, aM.w); aM.w = fmaf( xv.z, e.y, aM.w);
            }
            const int mP = pr*20 + 2*kp;
            const int mM = (40 - pr)*20 + 2*kp;
            g_Xf[(size_t)mP     * NBI + bi] = make_float2(aP.x, aP.y);
            g_Xf[(size_t)(mP+1) * NBI + bi] = make_float2(aP.z, aP.w);
            g_Xf[(size_t)mM     * NBI + bi] = make_float2(aM.x, aM.y);
            g_Xf[(size_t)(mM+1) * NBI + bi] = make_float2(aM.z, aM.w);
        }
    }
}

// ---------------------------------------------------------------------------
// Stage 3: channel mix, 2 modes per block. (unchanged)
// ---------------------------------------------------------------------------
__global__ void __launch_bounds__(256) stage3_mix(const float* __restrict__ w1re,
                                                 const float* __restrict__ w1im,
                                                 const float* __restrict__ w2re,
                                                 const float* __restrict__ w2im) {
    extern __shared__ float smem3[];
    float4* Ws  = (float4*)smem3;                 // [4096]
    float2* Xs0 = (float2*)(smem3 + 16384);       // [1024]
    float2* Xs1 = (float2*)(smem3 + 18432);       // [1024]

    const int bq  = blockIdx.x;                   // 0..399
    const int t   = threadIdx.x;
    const int j   = bq / 10;
    const int kyg = bq % 10;
    const int m0  = j*20 + 2*kyg;

    const float* wre; const float* wim; int off;
    if (j < 20) { wre = w1re; wim = w1im; off = j*20 + 2*kyg; }
    else        { wre = w2re; wim = w2im; off = (j-20)*20 + 2*kyg; }

    for (int io = t; io < 4096; io += 256) {
        float2 r2 = *(const float2*)(wre + (size_t)io*400 + off);
        float2 i2 = *(const float2*)(wim + (size_t)io*400 + off);
        Ws[io] = make_float4(r2.x, i2.x, r2.y, i2.y);
    }
    for (int i = t; i < 1024; i += 256) {
        Xs0[i] = g_Xf[(size_t)m0     * NBI + i];
        Xs1[i] = g_Xf[(size_t)(m0+1) * NBI + i];
    }
    __syncthreads();

    const int o  = t & 63;
    const int xb = (t >> 6) << 6;
    float a0R[4], a0I[4], a1R[4], a1I[4];
    #pragma unroll
    for (int k = 0; k < 4; k++) { a0R[k]=0.f; a0I[k]=0.f; a1R[k]=0.f; a1I[k]=0.f; }

    #pragma unroll 4
    for (int i = 0; i < 64; i++) {
        float4 wv = Ws[i*64 + o];
        #pragma unroll
        for (int k = 0; k < 4; k++) {
            float2 x0 = Xs0[xb + k*256 + i];
            a0R[k] = fmaf(x0.x, wv.x, a0R[k]); a0R[k] = fmaf(-x0.y, wv.y, a0R[k]);
            a0I[k] = fmaf(x0.x, wv.y, a0I[k]); a0I[k] = fmaf( x0.y, wv.x, a0I[k]);
            float2 x1 = Xs1[xb + k*256 + i];
            a1R[k] = fmaf(x1.x, wv.z, a1R[k]); a1R[k] = fmaf(-x1.y, wv.w, a1R[k]);
            a1I[k] = fmaf(x1.x, wv.w, a1I[k]); a1I[k] = fmaf( x1.y, wv.z, a1I[k]);
        }
    }
    float4* Y4 = (float4*)g_Yf;
    #pragma unroll
    for (int k = 0; k < 4; k++) {
        size_t base = ((size_t)(t + k*256) * NMODE + m0) >> 1;
        Y4[base] = make_float4(a0R[k], a0I[k], a1R[k], a1I[k]);
    }
}

// ---------------------------------------------------------------------------
// Kernel B: fused inverse H-DFT + c2r. 256 threads, 2 CTA/SM. Packed f32x2.
// Phase A: conjugate-pair blocked; SD stored (S.re, S.im, -D.im, D.re).
// Phase B: w-reflection split; packed twiddles cs=(c,s), sw=(s,c).
// smem (floats):
//   Ys   [0,10240)       float2[256][20] (Yfs raw occupies [0,1600) first)
//   SD4  [10240,11760)   float4[380]
//   j0r  [11760,11800)   float2[20]
//   j20r [11800,11880)   float4[20]  (y.x, y.y, -y.y, y.x)
//   eb   [11880,12392)   float2[256]
// ---------------------------------------------------------------------------
__global__ void __launch_bounds__(256, 2) stage45_bwd(float* __restrict__ out) {
    extern __shared__ float smemb[];
    float2* Yfs  = (float2*)smemb;                 // [800] raw (dead after prep)
    float2* Ys   = (float2*)smemb;                 // [256][20]
    float4* SD4  = (float4*)(smemb + 10240);       // [380]
    float2* j0r  = (float2*)(smemb + 11760);       // [20]
    float4* j20r = (float4*)(smemb + 11800);       // [20]
    float2* eb   = (float2*)(smemb + 11880);       // [256]

    const int bo = blockIdx.x;
    const int t  = threadIdx.x;

    for (int i = t; i < NMODE; i += 256) Yfs[i] = g_Yf[(size_t)bo * NMODE + i];
    {
        float s, c;
        sincospif((float)t * (1.0f/128.0f), &s, &c);
        eb[t] = make_float2(c, s);
    }
    __syncthreads();

    // prep: SD = (S.re, S.im, -D.im, D.re); singles j0, j20 (packed for fma2)
    for (int i = t; i < 380; i += 256) {
        int pr = i / 20 + 1;
        int ky = i % 20;
        float2 Yp = Yfs[pr*20 + ky];
        float2 Ym = Yfs[(40 - pr)*20 + ky];
        SD4[i] = make_float4(Yp.x + Ym.x, Yp.y + Ym.y, -(Yp.y - Ym.y), Yp.x - Ym.x);
    }
    if (t < 20) {
        j0r[t] = Yfs[t];
        float2 y = Yfs[400 + t];
        j20r[t] = make_float4(y.x, y.y, -y.y, y.x);
    }
    __syncthreads();

    // Phase A (packed)
    {
        const int hh     = t & 127;
        const int kybase = (t >> 7) * 10;
        const ulonglong2* SD8 = (const ulonglong2*)SD4;

        u64 aE[10], aO[10];
        #pragma unroll
        for (int k = 0; k < 10; k++) {
            float2 y0 = j0r[kybase + k];
            aE[k] = pk2(y0.x, y0.y);
            aO[k] = 0ull;
        }

        // odd pr pairs -> O
        #pragma unroll 2
        for (int pp = 0; pp < 10; pp++) {
            const int pr = 2*pp + 1;
            float2 e = eb[(pr * hh) & 255];
            u64 exx = pk2(e.x, e.x), eyy = pk2(e.y, e.y);
            const ulonglong2* fp = SD8 + (pr - 1)*20 + kybase;
            #pragma unroll
            for (int k = 0; k < 10; k++) {
                ulonglong2 f = fp[k];              // broadcast
                aO[k] = ffma2(f.x, exx, aO[k]);
                aO[k] = ffma2(f.y, eyy, aO[k]);
            }
        }
        // even pr pairs -> E
        #pragma unroll 2
        for (int pp = 1; pp <= 9; pp++) {
            const int pr = 2*pp;
            float2 e = eb[(pr * hh) & 255];
            u64 exx = pk2(e.x, e.x), eyy = pk2(e.y, e.y);
            const ulonglong2* fp = SD8 + (pr - 1)*20 + kybase;
            #pragma unroll
            for (int k = 0; k < 10; k++) {
                ulonglong2 f = fp[k];
                aE[k] = ffma2(f.x, exx, aE[k]);
                aE[k] = ffma2(f.y, eyy, aE[k]);
            }
        }
        // lone kx=236 (even parity)
        {
            float2 e = eb[(236 * hh) & 255];
            u64 exx = pk2(e.x, e.x), eyy = pk2(e.y, e.y);
            const ulonglong2* jp = (const ulonglong2*)j20r;
            #pragma unroll
            for (int k = 0; k < 10; k++) {
                ulonglong2 y = jp[kybase + k];
                aE[k] = ffma2(y.x, exx, aE[k]);
                aE[k] = ffma2(y.y, eyy, aE[k]);
            }
        }

        const float sc1 = 1.0f / 65536.0f;
        const float sc2 = 2.0f / 65536.0f;
        #pragma unroll
        for (int k = 0; k < 10; k++) {
            int ky  = kybase + k;
            float s = (ky == 0) ? sc1 : sc2;
            float er, ei, orr, oi;
            upk2(aE[k], er, ei);
            upk2(aO[k], orr, oi);
            Ys[ hh       *20 + ky] = make_float2((er + orr)*s, (ei + oi)*s);
            Ys[(hh + 128)*20 + ky] = make_float2((er - orr)*s, (ei - oi)*s);
        }
        __syncthreads();
    }

    // Phase B: reflection-split c2r, packed
    {
        const int lane = t & 31;
        const int w    = lane + 1;          // 1..32
        const int qr   = t >> 5;            // 0..7 -> rows qr*32..qr*32+31

        u64 cs2[20], sw2[10];
        #pragma unroll
        for (int ky = 0; ky < 20; ky++) {
            float s, c;
            sincospif((float)(ky * w) * (1.0f/128.0f), &s, &c);
            cs2[ky] = pk2(c, s);
            if (ky & 1) sw2[ky >> 1] = pk2(s, c);
        }

        float* outb = out + (size_t)bo * (HH*WW);
        const ulonglong2* y8 = (const ulonglong2*)Ys;
        const float4*     y4 = (const float4*)Ys;

        #pragma unroll 2
        for (int rr = 0; rr < 32; rr++) {
            const int r = qr*32 + rr;
            u64 P0 = 0ull, P2 = 0ull, Pa1 = 0ull, Qa1 = 0ull, Pa3 = 0ull, Qa3 = 0ull;
            #pragma unroll
            for (int qq = 0; qq < 5; qq++) {
                ulonglong2 a = y8[r*10 + 2*qq];          // (re0,im0 | re1,im1)
                P0  = ffma2(a.x, cs2[4*qq    ], P0);
                Pa1 = ffma2(a.y, cs2[4*qq + 1], Pa1);
                Qa1 = ffma2(a.y, sw2[2*qq    ], Qa1);
                ulonglong2 b = y8[r*10 + 2*qq + 1];
                P2  = ffma2(b.x, cs2[4*qq + 2], P2);
                Pa3 = ffma2(b.y, cs2[4*qq + 3], Pa3);
                Qa3 = ffma2(b.y, sw2[2*qq + 1], Qa3);
            }
            float c0, s0, c2, s2, ca1, sb1, sa1, cb1, ca3, sb3, sa3, cb3;
            upk2(P0, c0, s0);   upk2(P2, c2, s2);
            upk2(Pa1, ca1, sb1); upk2(Qa1, sa1, cb1);
            upk2(Pa3, ca3, sb3); upk2(Qa3, sa3, cb3);

            const float U0 = c0 - s0,  U0p = c0 + s0;
            const float U2 = c2 - s2,  U2p = c2 + s2;
            const float U1 = ca1 - sb1, U1p = ca1 + sb1;
            const float V1 = sa1 + cb1, V1p = sa1 - cb1;
            const float U3 = ca3 - sb3, U3p = ca3 + sb3;
            const float V3 = sa3 + cb3, V3p = sa3 - cb3;
            float* ro = outb + r*256;
            ro[w      ] = U0 + U1 + U2 + U3;
            ro[w + 64 ] = U0 - V1 - U2 + V3;
            ro[w + 128] = U0 - U1 + U2 - U3;
            ro[w + 192] = U0 + V1 - U2 - V3;
            ro[64  - w] = U0p + V1p - U2p - V3p;
            ro[128 - w] = U0p - U1p + U2p - U3p;
            ro[192 - w] = U0p - V1p - U2p + V3p;
            ro[256 - w] = U0p + U1p + U2p + U3p;
        }

        // tail: columns {0,64,128,192}, one row per thread, adds only
        {
            const int r = t;
            float R0=0.f,R1=0.f,R2=0.f,R3=0.f,I1=0.f,I3=0.f;
            #pragma unroll
            for (int qq = 0; qq < 5; qq++) {
                float4 a = y4[r*10 + 2*qq];
                R0 += a.x; R1 += a.z; I1 += a.w;
                float4 b = y4[r*10 + 2*qq + 1];
                R2 += b.x; R3 += b.z; I3 += b.w;
            }
            float* ro = outb + r*256;
            ro[0  ] = R0 + R1 + R2 + R3;
            ro[64 ] = R0 - I1 - R2 + I3;
            ro[128] = R0 - R1 + R2 - R3;
            ro[192] = R0 + I1 - R2 - I3;
        }
    }
}

// ---------------------------------------------------------------------------
extern "C" void kernel_launch(void* const* d_in, const int* in_sizes, int n_in,
                              void* d_out, int out_size) {
    const float* x    = (const float*)d_in[0];
    const float* w1re = (const float*)d_in[1];
    const float* w1im = (const float*)d_in[2];
    const float* w2re = (const float*)d_in[3];
    const float* w2im = (const float*)d_in[4];
    float* out = (float*)d_out;

    const int sA = 61440;
    const int s3 = 81920;
    const int sB = 49664;   // Ys 40960 + SD 6080 + j0 160 + j20 320 + eb 2048 (+pad)
    cudaFuncSetAttribute(stage12_fwd, cudaFuncAttributeMaxDynamicSharedMemorySize, sA);
    cudaFuncSetAttribute(stage3_mix,  cudaFuncAttributeMaxDynamicSharedMemorySize, s3);
    cudaFuncSetAttribute(stage45_bwd, cudaFuncAttributeMaxDynamicSharedMemorySize, sB);

    stage12_fwd<<<NBI, 256, sA>>>(x);
    stage3_mix <<<400, 256, s3>>>(w1re, w1im, w2re, w2im);
    stage45_bwd<<<NBO, 256, sB>>>(out);
}

// round 16
// speedup vs baseline: 1.1009x; 1.0141x over previous
#include <cuda_runtime.h>
#include <math.h>

#define BB   16
#define CIN  64
#define COUT 64
#define HH   256
#define WW   256
#define NMODE 800        // 40 kx * 20 ky
#define NBI  1024        // B*CI
#define NBO  1024        // B*CO

typedef unsigned long long u64;

__device__ __forceinline__ u64 pk2(float lo, float hi) {
    u64 r; asm("mov.b64 %0, {%1,%2};" : "=l"(r) : "f"(lo), "f"(hi)); return r;
}
__device__ __forceinline__ void upk2(u64 v, float& lo, float& hi) {
    asm("mov.b64 {%0,%1}, %2;" : "=f"(lo), "=f"(hi) : "l"(v));
}
__device__ __forceinline__ u64 ffma2(u64 a, u64 b, u64 c) {
    u64 d; asm("fma.rn.f32x2 %0, %1, %2, %3;" : "=l"(d) : "l"(a), "l"(b), "l"(c)); return d;
}

__device__ float2 g_Xf[NMODE * NBI];       // [m][bi]  6.6 MB
__device__ float2 g_Yf[NBO * NMODE];       // [bo][m]  6.6 MB

// ---------------------------------------------------------------------------
// Kernel A: fused W-DFT + H-DFT. 256 threads, 2 CTA/SM.
// (R12 scalar configuration restored verbatim: best measured 133 us.)
// ---------------------------------------------------------------------------
__global__ void __launch_bounds__(256, 2) stage12_fwd(const float* __restrict__ x) {
    extern __shared__ float smem[];
    float*  Ef  = smem;                            // [256*12]
    float*  Of  = smem + 3072;
    float*  EMf = smem + 6144;
    float*  OMf = smem + 9216;
    float4* tw4 = (float4*)(smem + 12288);         // [64][10]
    float2* eb  = (float2*)(smem + 14848);         // [256]
    float4* Xs4 = (float4*)smem;                   // [128][11] (phase-2 input)
    float4* Xd4 = Xs4 + 1408;

    const int bi  = blockIdx.x;
    const int t   = threadIdx.x;
    const int rp  = t & 127;
    const int kyh = t >> 7;                        // warp-uniform ky half

    for (int i = t; i < 640; i += 256) {
        int wi = i / 10 + 1, kk = i % 10;
        float s0, c0, s1, c1;
        sincospif((float)((2*kk    ) * wi) * (1.0f/128.0f), &s0, &c0);
        sincospif((float)((2*kk + 1) * wi) * (1.0f/128.0f), &s1, &c1);
        float hsc = (wi == 64) ? 0.5f : 1.0f;
        tw4[i] = make_float4(c0*hsc, s0*hsc, c1*hsc, s1*hsc);
    }
    {
        float s, c;
        sincospif((float)t * (1.0f/128.0f), &s, &c);
        eb[t] = make_float2(c, s);
    }

    const float* img = x + (size_t)bi * (HH*WW);

    float4 acc0[5], acc1[5];
    {
        float a0 = img[rp*WW],         b0 = img[rp*WW + 128];
        float a1 = img[(rp+128)*WW],   b1 = img[(rp+128)*WW + 128];
        float ue0 = a0 + b0, uo0 = a0 - b0;
        float ue1 = a1 + b1, uo1 = a1 - b1;
        #pragma unroll
        for (int k = 0; k < 5; k++) {
            acc0[k] = make_float4(ue0, 0.f, uo0, 0.f);   // w=0 term (c=1,s=0)
            acc1[k] = make_float4(ue1, 0.f, uo1, 0.f);
        }
    }

    for (int c = 0; c < 8; c++) {                  // chunks of 8 w, w = 1..64
        const int w0     = 1 + 8*c;
        const int mstart = 120 - 8*c;              // mirror window start
        __syncthreads();
        #pragma unroll
        for (int i = 0; i < 8; i++) {
            int idx = t + i*256;                   // 0..2047
            int r   = idx >> 3;
            int j   = idx & 7;
            const float* rpn = img + r * WW;
            float a1 = rpn[w0 + j],     b1 = rpn[w0 + j + 128];
            float a2 = rpn[mstart + j], b2 = rpn[mstart + j + 128];
            int s = r*12 + j;
            Ef[s]  = a1 + b1;  Of[s]  = a1 - b1;
            EMf[s] = a2 + b2;  OMf[s] = a2 - b2;
        }
        __syncthreads();

        const float4* E4  = (const float4*)Ef;
        const float4* O4  = (const float4*)Of;
        const float4* EM4 = (const float4*)EMf;
        const float4* OM4 = (const float4*)OMf;
        #pragma unroll
        for (int g = 0; g < 2; g++) {
            float4 e0  = E4 [rp*3 + g];
            float4 o0  = O4 [rp*3 + g];
            float4 em0 = EM4[rp*3 + (1-g)];
            float4 om0 = OM4[rp*3 + (1-g)];
            float4 e1  = E4 [(rp+128)*3 + g];
            float4 o1  = O4 [(rp+128)*3 + g];
            float4 em1 = EM4[(rp+128)*3 + (1-g)];
            float4 om1 = OM4[(rp+128)*3 + (1-g)];
            const float ev0[4]  = {e0.x,  e0.y,  e0.z,  e0.w};
            const float ov0[4]  = {o0.x,  o0.y,  o0.z,  o0.w};
            const float emv0[4] = {em0.x, em0.y, em0.z, em0.w};
            const float omv0[4] = {om0.x, om0.y, om0.z, om0.w};
            const float ev1[4]  = {e1.x,  e1.y,  e1.z,  e1.w};
            const float ov1[4]  = {o1.x,  o1.y,  o1.z,  o1.w};
            const float emv1[4] = {em1.x, em1.y, em1.z, em1.w};
            const float omv1[4] = {om1.x, om1.y, om1.z, om1.w};
            const int tb = (8*c + 4*g)*10 + kyh*5;
            #pragma unroll
            for (int jj = 0; jj < 4; jj++) {
                const float se0 = ev0[jj] + emv0[3-jj];
                const float de0 = ev0[jj] - emv0[3-jj];
                const float so0 = ov0[jj] + omv0[3-jj];
                const float do0 = ov0[jj] - omv0[3-jj];
                const float se1 = ev1[jj] + emv1[3-jj];
                const float de1 = ev1[jj] - emv1[3-jj];
                const float so1 = ov1[jj] + omv1[3-jj];
                const float do1 = ov1[jj] - omv1[3-jj];
                #pragma unroll
                for (int k = 0; k < 5; k++) {
                    float4 tv = tw4[tb + jj*10 + k];   // broadcast
                    acc0[k].x = fmaf( se0, tv.x, acc0[k].x);
                    acc0[k].y = fmaf(-de0, tv.y, acc0[k].y);
                    acc0[k].z = fmaf( do0, tv.z, acc0[k].z);
                    acc0[k].w = fmaf(-so0, tv.w, acc0[k].w);
                    acc1[k].x = fmaf( se1, tv.x, acc1[k].x);
                    acc1[k].y = fmaf(-de1, tv.y, acc1[k].y);
                    acc1[k].z = fmaf( do1, tv.z, acc1[k].z);
                    acc1[k].w = fmaf(-so1, tv.w, acc1[k].w);
                }
            }
        }
    }

    // h-fold in registers (rows rp / rp+128), store Xsum/Xdif at pitch 11
    __syncthreads();
    #pragma unroll
    for (int k = 0; k < 5; k++) {
        const int idx = rp*11 + kyh*5 + k;
        Xs4[idx] = make_float4(acc0[k].x + acc1[k].x, acc0[k].y + acc1[k].y,
                               acc0[k].z + acc1[k].z, acc0[k].w + acc1[k].w);
        Xd4[idx] = make_float4(acc0[k].x - acc1[k].x, acc0[k].y - acc1[k].y,
                               acc0[k].z - acc1[k].z, acc0[k].w - acc1[k].w);
    }
    __syncthreads();

    // Phase 2: conjugate-pair blocked H-DFT. 210 active threads.
    if (t < 210) {
        const int pr = t / 10;                      // 0..20
        const int kp = t % 10;

        if (pr == 0) {
            const float4* Xp = Xs4;
            float4 acc = make_float4(0.f, 0.f, 0.f, 0.f);
            #pragma unroll 8
            for (int h = 0; h < 128; h++) {
                float4 xv = Xp[h*11 + kp];
                acc.x += xv.x; acc.y += xv.y; acc.z += xv.z; acc.w += xv.w;
            }
            const int m0 = 2*kp;
            g_Xf[(size_t)m0     * NBI + bi] = make_float2(acc.x, acc.y);
            g_Xf[(size_t)(m0+1) * NBI + bi] = make_float2(acc.z, acc.w);
        } else if (pr == 20) {
            const float4* Xp = Xs4;                 // kx=236 even parity
            float4 acc = make_float4(0.f, 0.f, 0.f, 0.f);
            int p = 0;
            #pragma unroll 8
            for (int h = 0; h < 128; h++) {
                float2 e  = eb[p];
                p = (p + 236) & 255;
                float4 xv = Xp[h*11 + kp];
                acc.x = fmaf(xv.x, e.x, acc.x); acc.x = fmaf( xv.y, e.y, acc.x);
                acc.y = fmaf(xv.y, e.x, acc.y); acc.y = fmaf(-xv.x, e.y, acc.y);
                acc.z = fmaf(xv.z, e.x, acc.z); acc.z = fmaf( xv.w, e.y, acc.z);
                acc.w = fmaf(xv.w, e.x, acc.w); acc.w = fmaf(-xv.z, e.y, acc.w);
            }
            const int m0 = 20*20 + 2*kp;
            g_Xf[(size_t)m0     * NBI + bi] = make_float2(acc.x, acc.y);
            g_Xf[(size_t)(m0+1) * NBI + bi] = make_float2(acc.z, acc.w);
        } else {
            const float4* Xp = (pr & 1) ? Xd4 : Xs4;
            float4 aP = make_float4(0.f, 0.f, 0.f, 0.f);
            float4 aM = make_float4(0.f, 0.f, 0.f, 0.f);
            int p = 0;
            #pragma unroll 4
            for (int h = 0; h < 128; h++) {
                float2 e  = eb[p];
                p = (p + pr) & 255;
                float4 xv = Xp[h*11 + kp];
                aP.x = fmaf(xv.x, e.x, aP.x); aP.x = fmaf( xv.y, e.y, aP.x);
                aP.y = fmaf(xv.y, e.x, aP.y); aP.y = fmaf(-xv.x, e.y, aP.y);
                aP.z = fmaf(xv.z, e.x, aP.z); aP.z = fmaf( xv.w, e.y, aP.z);
                aP.w = fmaf(xv.w, e.x, aP.w); aP.w = fmaf(-xv.z, e.y, aP.w);
                aM.x = fmaf(xv.x, e.x, aM.x); aM.x = fmaf(-xv.y, e.y, aM.x);
                aM.y = fmaf(xv.y, e.x, aM.y); aM.y = fmaf( xv.x, e.y, aM.y);
                aM.z = fmaf(xv.z, e.x, aM.z); aM.z = fmaf(-xv.w, e.y, aM.z);
                aM.w = fmaf(xv.w, e.x, aM.w); aM.w = fmaf( xv.z, e.y, aM.w);
            }
            const int mP = pr*20 + 2*kp;
            const int mM = (40 - pr)*20 + 2*kp;
            g_Xf[(size_t)mP     * NBI + bi] = make_float2(aP.x, aP.y);
            g_Xf[(size_t)(mP+1) * NBI + bi] = make_float2(aP.z, aP.w);
            g_Xf[(size_t)mM     * NBI + bi] = make_float2(aM.x, aM.y);
            g_Xf[(size_t)(mM+1) * NBI + bi] = make_float2(aM.z, aM.w);
        }
    }
}

// ---------------------------------------------------------------------------
// Stage 3: channel mix, 2 modes per block. (unchanged)
// ---------------------------------------------------------------------------
__global__ void __launch_bounds__(256) stage3_mix(const float* __restrict__ w1re,
                                                 const float* __restrict__ w1im,
                                                 const float* __restrict__ w2re,
                                                 const float* __restrict__ w2im) {
    extern __shared__ float smem3[];
    float4* Ws  = (float4*)smem3;                 // [4096]
    float2* Xs0 = (float2*)(smem3 + 16384);       // [1024]
    float2* Xs1 = (float2*)(smem3 + 18432);       // [1024]

    const int bq  = blockIdx.x;                   // 0..399
    const int t   = threadIdx.x;
    const int j   = bq / 10;
    const int kyg = bq % 10;
    const int m0  = j*20 + 2*kyg;

    const float* wre; const float* wim; int off;
    if (j < 20) { wre = w1re; wim = w1im; off = j*20 + 2*kyg; }
    else        { wre = w2re; wim = w2im; off = (j-20)*20 + 2*kyg; }

    for (int io = t; io < 4096; io += 256) {
        float2 r2 = *(const float2*)(wre + (size_t)io*400 + off);
        float2 i2 = *(const float2*)(wim + (size_t)io*400 + off);
        Ws[io] = make_float4(r2.x, i2.x, r2.y, i2.y);
    }
    for (int i = t; i < 1024; i += 256) {
        Xs0[i] = g_Xf[(size_t)m0     * NBI + i];
        Xs1[i] = g_Xf[(size_t)(m0+1) * NBI + i];
    }
    __syncthreads();

    const int o  = t & 63;
    const int xb = (t >> 6) << 6;
    float a0R[4], a0I[4], a1R[4], a1I[4];
    #pragma unroll
    for (int k = 0; k < 4; k++) { a0R[k]=0.f; a0I[k]=0.f; a1R[k]=0.f; a1I[k]=0.f; }

    #pragma unroll 4
    for (int i = 0; i < 64; i++) {
        float4 wv = Ws[i*64 + o];
        #pragma unroll
        for (int k = 0; k < 4; k++) {
            float2 x0 = Xs0[xb + k*256 + i];
            a0R[k] = fmaf(x0.x, wv.x, a0R[k]); a0R[k] = fmaf(-x0.y, wv.y, a0R[k]);
            a0I[k] = fmaf(x0.x, wv.y, a0I[k]); a0I[k] = fmaf( x0.y, wv.x, a0I[k]);
            float2 x1 = Xs1[xb + k*256 + i];
            a1R[k] = fmaf(x1.x, wv.z, a1R[k]); a1R[k] = fmaf(-x1.y, wv.w, a1R[k]);
            a1I[k] = fmaf(x1.x, wv.w, a1I[k]); a1I[k] = fmaf( x1.y, wv.z, a1I[k]);
        }
    }
    float4* Y4 = (float4*)g_Yf;
    #pragma unroll
    for (int k = 0; k < 4; k++) {
        size_t base = ((size_t)(t + k*256) * NMODE + m0) >> 1;
        Y4[base] = make_float4(a0R[k], a0I[k], a1R[k], a1I[k]);
    }
}

// ---------------------------------------------------------------------------
// Kernel B: fused inverse H-DFT + c2r. 256 threads, 2 CTA/SM. Packed f32x2.
// (R15 configuration: measured best for this kernel. Unchanged.)
// ---------------------------------------------------------------------------
__global__ void __launch_bounds__(256, 2) stage45_bwd(float* __restrict__ out) {
    extern __shared__ float smemb[];
    float2* Yfs  = (float2*)smemb;                 // [800] raw (dead after prep)
    float2* Ys   = (float2*)smemb;                 // [256][20]
    float4* SD4  = (float4*)(smemb + 10240);       // [380]
    float2* j0r  = (float2*)(smemb + 11760);       // [20]
    float4* j20r = (float4*)(smemb + 11800);       // [20]
    float2* eb   = (float2*)(smemb + 11880);       // [256]

    const int bo = blockIdx.x;
    const int t  = threadIdx.x;

    for (int i = t; i < NMODE; i += 256) Yfs[i] = g_Yf[(size_t)bo * NMODE + i];
    {
        float s, c;
        sincospif((float)t * (1.0f/128.0f), &s, &c);
        eb[t] = make_float2(c, s);
    }
    __syncthreads();

    for (int i = t; i < 380; i += 256) {
        int pr = i / 20 + 1;
        int ky = i % 20;
        float2 Yp = Yfs[pr*20 + ky];
        float2 Ym = Yfs[(40 - pr)*20 + ky];
        SD4[i] = make_float4(Yp.x + Ym.x, Yp.y + Ym.y, -(Yp.y - Ym.y), Yp.x - Ym.x);
    }
    if (t < 20) {
        j0r[t] = Yfs[t];
        float2 y = Yfs[400 + t];
        j20r[t] = make_float4(y.x, y.y, -y.y, y.x);
    }
    __syncthreads();

    // Phase A (packed)
    {
        const int hh     = t & 127;
        const int kybase = (t >> 7) * 10;
        const ulonglong2* SD8 = (const ulonglong2*)SD4;

        u64 aE[10], aO[10];
        #pragma unroll
        for (int k = 0; k < 10; k++) {
            float2 y0 = j0r[kybase + k];
            aE[k] = pk2(y0.x, y0.y);
            aO[k] = 0ull;
        }

        #pragma unroll 2
        for (int pp = 0; pp < 10; pp++) {
            const int pr = 2*pp + 1;
            float2 e = eb[(pr * hh) & 255];
            u64 exx = pk2(e.x, e.x), eyy = pk2(e.y, e.y);
            const ulonglong2* fp = SD8 + (pr - 1)*20 + kybase;
            #pragma unroll
            for (int k = 0; k < 10; k++) {
                ulonglong2 f = fp[k];
                aO[k] = ffma2(f.x, exx, aO[k]);
                aO[k] = ffma2(f.y, eyy, aO[k]);
            }
        }
        #pragma unroll 2
        for (int pp = 1; pp <= 9; pp++) {
            const int pr = 2*pp;
            float2 e = eb[(pr * hh) & 255];
            u64 exx = pk2(e.x, e.x), eyy = pk2(e.y, e.y);
            const ulonglong2* fp = SD8 + (pr - 1)*20 + kybase;
            #pragma unroll
            for (int k = 0; k < 10; k++) {
                ulonglong2 f = fp[k];
                aE[k] = ffma2(f.x, exx, aE[k]);
                aE[k] = ffma2(f.y, eyy, aE[k]);
            }
        }
        {
            float2 e = eb[(236 * hh) & 255];
            u64 exx = pk2(e.x, e.x), eyy = pk2(e.y, e.y);
            const ulonglong2* jp = (const ulonglong2*)j20r;
            #pragma unroll
            for (int k = 0; k < 10; k++) {
                ulonglong2 y = jp[kybase + k];
                aE[k] = ffma2(y.x, exx, aE[k]);
                aE[k] = ffma2(y.y, eyy, aE[k]);
            }
        }

        const float sc1 = 1.0f / 65536.0f;
        const float sc2 = 2.0f / 65536.0f;
        #pragma unroll
        for (int k = 0; k < 10; k++) {
            int ky  = kybase + k;
            float s = (ky == 0) ? sc1 : sc2;
            float er, ei, orr, oi;
            upk2(aE[k], er, ei);
            upk2(aO[k], orr, oi);
            Ys[ hh       *20 + ky] = make_float2((er + orr)*s, (ei + oi)*s);
            Ys[(hh + 128)*20 + ky] = make_float2((er - orr)*s, (ei - oi)*s);
        }
        __syncthreads();
    }

    // Phase B: reflection-split c2r, packed
    {
        const int lane = t & 31;
        const int w    = lane + 1;          // 1..32
        const int qr   = t >> 5;            // 0..7 -> rows qr*32..qr*32+31

        u64 cs2[20], sw2[10];
        #pragma unroll
        for (int ky = 0; ky < 20; ky++) {
            float s, c;
            sincospif((float)(ky * w) * (1.0f/128.0f), &s, &c);
            cs2[ky] = pk2(c, s);
            if (ky & 1) sw2[ky >> 1] = pk2(s, c);
        }

        float* outb = out + (size_t)bo * (HH*WW);
        const ulonglong2* y8 = (const ulonglong2*)Ys;
        const float4*     y4 = (const float4*)Ys;

        #pragma unroll 2
        for (int rr = 0; rr < 32; rr++) {
            const int r = qr*32 + rr;
            u64 P0 = 0ull, P2 = 0ull, Pa1 = 0ull, Qa1 = 0ull, Pa3 = 0ull, Qa3 = 0ull;
            #pragma unroll
            for (int qq = 0; qq < 5; qq++) {
                ulonglong2 a = y8[r*10 + 2*qq];
                P0  = ffma2(a.x, cs2[4*qq    ], P0);
                Pa1 = ffma2(a.y, cs2[4*qq + 1], Pa1);
                Qa1 = ffma2(a.y, sw2[2*qq    ], Qa1);
                ulonglong2 b = y8[r*10 + 2*qq + 1];
                P2  = ffma2(b.x, cs2[4*qq + 2], P2);
                Pa3 = ffma2(b.y, cs2[4*qq + 3], Pa3);
                Qa3 = ffma2(b.y, sw2[2*qq + 1], Qa3);
            }
            float c0, s0, c2, s2, ca1, sb1, sa1, cb1, ca3, sb3, sa3, cb3;
            upk2(P0, c0, s0);   upk2(P2, c2, s2);
            upk2(Pa1, ca1, sb1); upk2(Qa1, sa1, cb1);
            upk2(Pa3, ca3, sb3); upk2(Qa3, sa3, cb3);

            const float U0 = c0 - s0,  U0p = c0 + s0;
            const float U2 = c2 - s2,  U2p = c2 + s2;
            const float U1 = ca1 - sb1, U1p = ca1 + sb1;
            const float V1 = sa1 + cb1, V1p = sa1 - cb1;
            const float U3 = ca3 - sb3, U3p = ca3 + sb3;
            const float V3 = sa3 + cb3, V3p = sa3 - cb3;
            float* ro = outb + r*256;
            ro[w      ] = U0 + U1 + U2 + U3;
            ro[w + 64 ] = U0 - V1 - U2 + V3;
            ro[w + 128] = U0 - U1 + U2 - U3;
            ro[w + 192] = U0 + V1 - U2 - V3;
            ro[64  - w] = U0p + V1p - U2p - V3p;
            ro[128 - w] = U0p - U1p + U2p - U3p;
            ro[192 - w] = U0p - V1p - U2p + V3p;
            ro[256 - w] = U0p + U1p + U2p + U3p;
        }

        // tail: columns {0,64,128,192}, one row per thread, adds only
        {
            const int r = t;
            float R0=0.f,R1=0.f,R2=0.f,R3=0.f,I1=0.f,I3=0.f;
            #pragma unroll
            for (int qq = 0; qq < 5; qq++) {
                float4 a = y4[r*10 + 2*qq];
                R0 += a.x; R1 += a.z; I1 += a.w;
                float4 b = y4[r*10 + 2*qq + 1];
                R2 += b.x; R3 += b.z; I3 += b.w;
            }
            float* ro = outb + r*256;
            ro[0  ] = R0 + R1 + R2 + R3;
            ro[64 ] = R0 - I1 - R2 + I3;
            ro[128] = R0 - R1 + R2 - R3;
            ro[192] = R0 + I1 - R2 - I3;
        }
    }
}

// ---------------------------------------------------------------------------
extern "C" void kernel_launch(void* const* d_in, const int* in_sizes, int n_in,
                              void* d_out, int out_size) {
    const float* x    = (const float*)d_in[0];
    const float* w1re = (const float*)d_in[1];
    const float* w1im = (const float*)d_in[2];
    const float* w2re = (const float*)d_in[3];
    const float* w2im = (const float*)d_in[4];
    float* out = (float*)d_out;

    const int sA = 61440;
    const int s3 = 81920;
    const int sB = 49664;
    cudaFuncSetAttribute(stage12_fwd, cudaFuncAttributeMaxDynamicSharedMemorySize, sA);
    cudaFuncSetAttribute(stage3_mix,  cudaFuncAttributeMaxDynamicSharedMemorySize, s3);
    cudaFuncSetAttribute(stage45_bwd, cudaFuncAttributeMaxDynamicSharedMemorySize, sB);

    stage12_fwd<<<NBI, 256, sA>>>(x);
    stage3_mix <<<400, 256, s3>>>(w1re, w1im, w2re, w2im);
    stage45_bwd<<<NBO, 256, sB>>>(out);
}